// round 1
// baseline (speedup 1.0000x reference)
#include <cuda_runtime.h>
#include <math.h>

// Problem constants
#define BB 16
#define CC 3
#define TT 32
#define HH 224
#define WW 224
#define GS 32
#define GH 7
#define GW 7
#define NPF (GH*GW)          // 49 nodes per frame
#define NODES (TT*NPF)       // 1568
#define NPATCH (BB*TT*GH*GW) // 25088
#define NPP (CC*GS*GS)       // 3072 elements per patch
#define SORTN 4096
#define NEDGE 15962
#define XFLOATS (BB*NODES*10) // 250880

__device__ __forceinline__ int tau_t(int t) {
    int c = 0;
    if (t + 1 < TT) c++;
    if (t - 1 >= 0) c++;
    if (t + 2 < TT) c++;
    if (t - 2 >= 0) c++;
    return c;
}

__global__ void __launch_bounds__(256)
feat_kernel(const float* __restrict__ v, float* __restrict__ out)
{
    __shared__ float s[SORTN];
    __shared__ double red[8][4];

    const int p   = blockIdx.x;          // ((b*TT+t)*GH+i)*GW+j
    const int j   = p % GW;
    int tmp       = p / GW;
    const int i   = tmp % GH;
    tmp          /= GH;
    const int t   = tmp % TT;
    const int b   = tmp / TT;

    const int tid  = threadIdx.x;
    const int lane = tid & 31;
    const int warp = tid >> 5;

    // ---- load 3072 floats (96 rows x 32), accumulate raw power sums ----
    double S1 = 0.0, S2 = 0.0, S3 = 0.0, S4 = 0.0;
    #pragma unroll
    for (int r = warp; r < 96; r += 8) {
        int c = r >> 5;          // channel
        int y = r & 31;          // row within patch
        size_t base = ((((size_t)b * CC + c) * TT + t) * HH + (size_t)(i * GS + y)) * WW
                      + (size_t)(j * GS);
        float val = v[base + lane];
        s[r * 32 + lane] = val;
        double d  = (double)val;
        double d2 = d * d;
        S1 += d; S2 += d2; S3 += d2 * d; S4 += d2 * d2;
    }
    // pad for sort
    #pragma unroll
    for (int k = NPP + tid; k < SORTN; k += 256) s[k] = INFINITY;

    // warp reduce 4 sums
    #pragma unroll
    for (int off = 16; off > 0; off >>= 1) {
        S1 += __shfl_down_sync(0xffffffffu, S1, off);
        S2 += __shfl_down_sync(0xffffffffu, S2, off);
        S3 += __shfl_down_sync(0xffffffffu, S3, off);
        S4 += __shfl_down_sync(0xffffffffu, S4, off);
    }
    if (lane == 0) { red[warp][0] = S1; red[warp][1] = S2; red[warp][2] = S3; red[warp][3] = S4; }
    __syncthreads();

    // ---- bitonic sort of s[0..4096) ascending ----
    for (int k = 2; k <= SORTN; k <<= 1) {
        for (int jj = k >> 1; jj > 0; jj >>= 1) {
            #pragma unroll 4
            for (int idx = tid; idx < (SORTN >> 1); idx += 256) {
                int m  = ((idx & ~(jj - 1)) << 1) | (idx & (jj - 1));
                int pm = m | jj;
                bool up = ((m & k) == 0);
                float a = s[m], c = s[pm];
                if ((a > c) == up) { s[m] = c; s[pm] = a; }
            }
            __syncthreads();
        }
    }

    if (tid == 0) {
        double s1 = 0, s2 = 0, s3 = 0, s4 = 0;
        #pragma unroll
        for (int w = 0; w < 8; w++) { s1 += red[w][0]; s2 += red[w][1]; s3 += red[w][2]; s4 += red[w][3]; }
        const double n = (double)NPP;
        double mean = s1 / n;
        double c2 = s2 - n * mean * mean;                       // sum (x-mu)^2
        double c3 = s3 - 3.0 * mean * s2 + 2.0 * n * mean * mean * mean;
        double mean2 = mean * mean;
        double c4 = s4 - 4.0 * mean * s3 + 6.0 * mean2 * s2 - 3.0 * n * mean2 * mean2;
        double var  = c2 / (n - 1.0);
        double stdv = sqrt(var);
        double sd_eps = stdv + 1e-8;
        double energy = s2 / n;
        double rms  = sqrt(energy + 1e-8);
        double skew = (c3 / n) / (sd_eps * sd_eps * sd_eps);
        double kurt = (c4 / n) / (sd_eps * sd_eps * sd_eps * sd_eps) - 3.0;

        float mn  = s[0];
        float mx  = s[NPP - 1];
        float med = s[(NPP - 1) / 2];                  // s[1535]
        // q=0.25: pos=767.75 -> lo=767 fr=0.75 ; q=0.75: pos=2303.25 -> lo=2303 fr=0.25
        float q25 = s[767] * 0.25f + s[768] * 0.75f;
        float q75 = s[2303] * 0.75f + s[2304] * 0.25f;
        float iqr = q75 - q25;

        float* o = out + (size_t)p * 10;
        o[0] = (float)mean;
        o[1] = (float)stdv;
        o[2] = mn;
        o[3] = mx;
        o[4] = (float)energy;
        o[5] = (float)rms;
        o[6] = (float)skew;
        o[7] = (float)kurt;
        o[8] = med;
        o[9] = iqr;
    }
}

__global__ void edge_kernel(float* __restrict__ out)
{
    int node = blockIdx.x * blockDim.x + threadIdx.x;
    if (node >= NODES) return;
    int t   = node / NPF;
    int rem = node % NPF;
    int i   = rem / GW;
    int j   = rem % GW;

    // prefix offset: full frames before t
    int off = 0;
    for (int tp = 0; tp < t; tp++) off += 312 + NPF * tau_t(tp);
    // nodes before (i,j) within frame t
    int taut = tau_t(t);
    for (int k = 0; k < rem; k++) {
        int ii = k / GW, jj = k % GW;
        int ci = (ii == 0 || ii == GH - 1) ? 2 : 3;
        int cj = (jj == 0 || jj == GW - 1) ? 2 : 3;
        off += ci * cj - 1 + taut;
    }

    const int di[8] = {-1,-1,-1, 0, 0, 1, 1, 1};
    const int dj[8] = {-1, 0, 1,-1, 1,-1, 0, 1};
    int e = off;
    float fnode = (float)node;
    #pragma unroll
    for (int q = 0; q < 8; q++) {
        int ni = i + di[q], nj = j + dj[q];
        if (ni >= 0 && ni < GH && nj >= 0 && nj < GW) {
            out[e]         = fnode;
            out[NEDGE + e] = (float)(t * NPF + ni * GW + nj);
            e++;
        }
    }
    const int dts[4] = {1, -1, 2, -2};
    #pragma unroll
    for (int q = 0; q < 4; q++) {
        int tt2 = t + dts[q];
        if (tt2 >= 0 && tt2 < TT) {
            out[e]         = fnode;
            out[NEDGE + e] = (float)(tt2 * NPF + i * GW + j);
            e++;
        }
    }
}

extern "C" void kernel_launch(void* const* d_in, const int* in_sizes, int n_in,
                              void* d_out, int out_size)
{
    const float* video = (const float*)d_in[0];
    float* out = (float*)d_out;

    feat_kernel<<<NPATCH, 256>>>(video, out);

    // If the harness output also holds the flattened edge index (x first, ei second)
    if (out_size >= XFLOATS + 2 * NEDGE) {
        edge_kernel<<<(NODES + 255) / 256, 256>>>(out + XFLOATS);
    }
}

// round 2
// speedup vs baseline: 3.0985x; 3.0985x over previous
#include <cuda_runtime.h>
#include <math.h>
#include <stdint.h>

#define BB 16
#define CC 3
#define TT 32
#define HH 224
#define WW 224
#define GS 32
#define GH 7
#define GW 7
#define NPF 49
#define NODES 1568
#define NPATCH 25088
#define NPP 3072
#define NEDGE 15962
#define XFLOATS 250880

// Order-preserving float->uint transform (ascending)
__device__ __forceinline__ uint32_t xform(float f) {
    uint32_t u = __float_as_uint(f);
    return (u & 0x80000000u) ? ~u : (u | 0x80000000u);
}
__device__ __forceinline__ float unxform(uint32_t u) {
    u = (u & 0x80000000u) ? (u ^ 0x80000000u) : ~u;
    return __uint_as_float(u);
}

// Block-cooperative: find bin containing rank r in hist[0..nbins), nbins in {1024,2048}.
// Broadcasts {bin, rank_within_bin} via outp[0..1]. All 256 threads must call.
__device__ __forceinline__ void find_bucket(const int* hist, int nbins, int r,
                                            int* warp_s, int* outp)
{
    const int tid = threadIdx.x, lane = tid & 31, w = tid >> 5;
    const int bpt = nbins >> 8;
    const int base = tid * bpt;
    int local = 0;
    #pragma unroll 8
    for (int k = 0; k < bpt; k++) local += hist[base + k];
    int v = local;
    #pragma unroll
    for (int off = 1; off < 32; off <<= 1) {
        int n = __shfl_up_sync(0xffffffffu, v, off);
        if (lane >= off) v += n;
    }
    if (lane == 31) warp_s[w] = v;
    __syncthreads();
    if (tid == 0) {
        int acc = 0;
        #pragma unroll
        for (int k = 0; k < 8; k++) { int t = warp_s[k]; warp_s[k] = acc; acc += t; }
    }
    __syncthreads();
    int excl = warp_s[w] + (v - local);   // exclusive prefix of this thread's segment
    if (r >= excl && r < excl + local) {
        int rr = r - excl;
        #pragma unroll 8
        for (int k = 0; k < bpt; k++) {
            int c = hist[base + k];
            if (rr < c) { outp[0] = base + k; outp[1] = rr; break; }
            rr -= c;
        }
    }
    __syncthreads();
}

__global__ void __launch_bounds__(256)
feat_kernel(const float* __restrict__ v, float* __restrict__ out)
{
    __shared__ uint32_t s[NPP];
    __shared__ int hist[2048];
    __shared__ float rf[24];
    __shared__ float bc[6];       // mean, min, max, m2, m3, m4
    __shared__ int fb_warp[8];
    __shared__ int fb_out[2];

    const int p = blockIdx.x;                 // ((b*TT+t)*GH+i)*GW+j
    const int j = p % GW;
    int tmp = p / GW;
    const int i = tmp % GH;
    tmp /= GH;
    const int t = tmp % TT;
    const int b = tmp / TT;

    const int tid = threadIdx.x;
    const int lane = tid & 31;
    const int warp = tid >> 5;

    // ---- load 3072 floats (96 aligned 128B rows), sum/min/max, store transformed ----
    float sum = 0.f, mn = INFINITY, mx = -INFINITY;
    #pragma unroll
    for (int k = 0; k < 12; k++) {
        int r = warp + k * 8;                 // 0..95
        int c = r >> 5, y = r & 31;
        size_t base = ((((size_t)b * CC + c) * TT + t) * HH + (size_t)(i * GS + y)) * WW
                      + (size_t)(j * GS);
        float val = v[base + lane];
        sum += val;
        mn = fminf(mn, val);
        mx = fmaxf(mx, val);
        s[r * 32 + lane] = xform(val);
    }
    #pragma unroll
    for (int off = 16; off > 0; off >>= 1) {
        sum += __shfl_down_sync(0xffffffffu, sum, off);
        mn = fminf(mn, __shfl_down_sync(0xffffffffu, mn, off));
        mx = fmaxf(mx, __shfl_down_sync(0xffffffffu, mx, off));
    }
    if (lane == 0) { rf[warp] = sum; rf[8 + warp] = mn; rf[16 + warp] = mx; }
    // zero histogram while waiting
    #pragma unroll
    for (int z = tid; z < 2048; z += 256) hist[z] = 0;
    __syncthreads();
    if (tid == 0) {
        float S = 0.f, MN = INFINITY, MX = -INFINITY;
        #pragma unroll
        for (int w = 0; w < 8; w++) {
            S += rf[w]; MN = fminf(MN, rf[8 + w]); MX = fmaxf(MX, rf[16 + w]);
        }
        bc[0] = S * (1.0f / (float)NPP);
        bc[1] = MN; bc[2] = MX;
    }
    __syncthreads();
    const float mean = bc[0];

    // ---- pass 0: fused central-moment scan + 11-bit histogram ----
    float m2 = 0.f, m3 = 0.f, m4 = 0.f;
    #pragma unroll
    for (int k = 0; k < 12; k++) {
        uint32_t u = s[tid + k * 256];
        float x = unxform(u);
        float d = x - mean;
        float d2 = d * d;
        m2 += d2; m3 += d2 * d; m4 += d2 * d2;
        atomicAdd(&hist[u >> 21], 1);
    }
    #pragma unroll
    for (int off = 16; off > 0; off >>= 1) {
        m2 += __shfl_down_sync(0xffffffffu, m2, off);
        m3 += __shfl_down_sync(0xffffffffu, m3, off);
        m4 += __shfl_down_sync(0xffffffffu, m4, off);
    }
    if (lane == 0) { rf[warp] = m2; rf[8 + warp] = m3; rf[16 + warp] = m4; }
    __syncthreads();
    if (tid == 0) {
        float M2 = 0.f, M3 = 0.f, M4 = 0.f;
        #pragma unroll
        for (int w = 0; w < 8; w++) { M2 += rf[w]; M3 += rf[8 + w]; M4 += rf[16 + w]; }
        bc[3] = M2; bc[4] = M3; bc[5] = M4;
    }
    __syncthreads();

    // ---- exact rank selection at 5 ranks via 3-pass radix (11/11/10 bits) ----
    const int ranks[5] = {767, 768, 1535, 2303, 2304};
    uint32_t p11[5]; int r1v[5];
    #pragma unroll
    for (int k = 0; k < 5; k++) {
        find_bucket(hist, 2048, ranks[k], fb_warp, fb_out);
        p11[k] = (uint32_t)fb_out[0];
        r1v[k] = fb_out[1];
    }

    uint32_t p22[5]; int r2v[5];
    for (int k = 0; k < 5; k++) {
        if (k == 0 || p11[k] != p11[k - 1]) {
            #pragma unroll
            for (int z = tid; z < 2048; z += 256) hist[z] = 0;
            __syncthreads();
            uint32_t pf = p11[k];
            #pragma unroll
            for (int q = 0; q < 12; q++) {
                uint32_t u = s[tid + q * 256];
                if ((u >> 21) == pf) atomicAdd(&hist[(u >> 10) & 0x7FF], 1);
            }
            __syncthreads();
        }
        find_bucket(hist, 2048, r1v[k], fb_warp, fb_out);
        p22[k] = (p11[k] << 11) | (uint32_t)fb_out[0];
        r2v[k] = fb_out[1];
    }

    uint32_t key[5];
    for (int k = 0; k < 5; k++) {
        if (k == 0 || p22[k] != p22[k - 1]) {
            #pragma unroll
            for (int z = tid; z < 1024; z += 256) hist[z] = 0;
            __syncthreads();
            uint32_t pf = p22[k];
            #pragma unroll
            for (int q = 0; q < 12; q++) {
                uint32_t u = s[tid + q * 256];
                if ((u >> 10) == pf) atomicAdd(&hist[u & 0x3FF], 1);
            }
            __syncthreads();
        }
        find_bucket(hist, 1024, r2v[k], fb_warp, fb_out);
        key[k] = (p22[k] << 10) | (uint32_t)fb_out[0];
    }

    if (tid == 0) {
        const float n = (float)NPP;
        float M2 = bc[3], M3 = bc[4], M4 = bc[5];
        float MN = bc[1], MX = bc[2];
        float var = M2 / (n - 1.0f);
        float sd = sqrtf(var);
        float sde = sd + 1e-8f;
        float energy = M2 / n + mean * mean;
        float rms = sqrtf(energy + 1e-8f);
        float inv3 = 1.0f / (sde * sde * sde);
        float skew = (M3 / n) * inv3;
        float kurt = (M4 / n) * inv3 / sde - 3.0f;

        float v767 = unxform(key[0]), v768 = unxform(key[1]);
        float med  = unxform(key[2]);
        float v2303 = unxform(key[3]), v2304 = unxform(key[4]);
        float q25 = v767 * 0.25f + v768 * 0.75f;
        float q75 = v2303 * 0.75f + v2304 * 0.25f;

        float* o = out + (size_t)p * 10;
        o[0] = mean; o[1] = sd; o[2] = MN; o[3] = MX; o[4] = energy;
        o[5] = rms;  o[6] = skew; o[7] = kurt; o[8] = med; o[9] = q75 - q25;
    }
}

__device__ __forceinline__ int tau_t(int t) {
    int c = 0;
    if (t + 1 < TT) c++;
    if (t - 1 >= 0) c++;
    if (t + 2 < TT) c++;
    if (t - 2 >= 0) c++;
    return c;
}

__global__ void edge_kernel(float* __restrict__ out)
{
    int node = blockIdx.x * blockDim.x + threadIdx.x;
    if (node >= NODES) return;
    int t = node / NPF;
    int rem = node % NPF;
    int i = rem / GW;
    int j = rem % GW;

    // closed-form prefix offset
    int mt = t < 30 ? t : 30;
    int cum_tau = (t > 0 ? 2 : 0) + (t > 1 ? 3 : 0)
                + 4 * (mt > 2 ? (mt - 2) : 0) + (t > 30 ? 3 : 0);
    int taut = tau_t(t);
    int rowpref = (i == 0) ? 0 : (31 + 50 * (i - 1));
    int ci = (i == 0 || i == GH - 1) ? 2 : 3;
    int cumcj = (j > 0 ? 2 : 0) + 3 * (j > 1 ? (j - 1) : 0);
    int sp = rowpref + ci * cumcj - j;
    int off = 312 * t + 49 * cum_tau + sp + rem * taut;

    const int di[8] = {-1,-1,-1, 0, 0, 1, 1, 1};
    const int dj[8] = {-1, 0, 1,-1, 1,-1, 0, 1};
    int e = off;
    float fnode = (float)node;
    #pragma unroll
    for (int q = 0; q < 8; q++) {
        int ni = i + di[q], nj = j + dj[q];
        if (ni >= 0 && ni < GH && nj >= 0 && nj < GW) {
            out[e]         = fnode;
            out[NEDGE + e] = (float)(t * NPF + ni * GW + nj);
            e++;
        }
    }
    const int dts[4] = {1, -1, 2, -2};
    #pragma unroll
    for (int q = 0; q < 4; q++) {
        int tt2 = t + dts[q];
        if (tt2 >= 0 && tt2 < TT) {
            out[e]         = fnode;
            out[NEDGE + e] = (float)(tt2 * NPF + i * GW + j);
            e++;
        }
    }
}

extern "C" void kernel_launch(void* const* d_in, const int* in_sizes, int n_in,
                              void* d_out, int out_size)
{
    const float* video = (const float*)d_in[0];
    float* out = (float*)d_out;

    feat_kernel<<<NPATCH, 256>>>(video, out);

    if (out_size >= XFLOATS + 2 * NEDGE) {
        edge_kernel<<<(NODES + 255) / 256, 256>>>(out + XFLOATS);
    }
}

// round 3
// speedup vs baseline: 3.6266x; 1.1704x over previous
#include <cuda_runtime.h>
#include <math.h>
#include <stdint.h>

#define BB 16
#define CC 3
#define TT 32
#define HH 224
#define WW 224
#define GS 32
#define GH 7
#define GW 7
#define NPF 49
#define NODES 1568
#define NPATCH 25088
#define NPP 3072
#define NEDGE 15962
#define XFLOATS 250880

__device__ __forceinline__ uint32_t xform(float f) {
    uint32_t u = __float_as_uint(f);
    return (u & 0x80000000u) ? ~u : (u | 0x80000000u);
}
__device__ __forceinline__ float unxform(uint32_t u) {
    u = (u & 0x80000000u) ? (u ^ 0x80000000u) : ~u;
    return __uint_as_float(u);
}

__global__ void __launch_bounds__(256)
feat_kernel(const float* __restrict__ v, float* __restrict__ out)
{
    __shared__ uint32_t s[NPP];
    __shared__ int      hist[2048];      // becomes exclusive cumulative in place
    __shared__ uint32_t buf[NPP];
    __shared__ float    rf[24];
    __shared__ float    bc[6];           // mean,min,max,M2,M3,M4
    __shared__ int      wsum[8];
    __shared__ int      sel_nb;
    __shared__ int      sel_bin[5], sel_off[5], sel_cnt[5];
    __shared__ int      rk_d[5], rk_in[5];
    __shared__ int      dcur[5];
    __shared__ float    resv[5];

    const int p = blockIdx.x;            // ((b*TT+t)*GH+i)*GW+j
    const int j = p % GW;
    int tmp = p / GW;
    const int i = tmp % GH;
    tmp /= GH;
    const int t = tmp % TT;
    const int b = tmp / TT;

    const int tid  = threadIdx.x;
    const int lane = tid & 31;
    const int warp = tid >> 5;

    // zero histogram
    #pragma unroll
    for (int z = tid; z < 2048; z += 256) hist[z] = 0;
    __syncthreads();

    // ---- load 3072 floats (96 aligned 128B rows): sum/min/max, xform->smem,
    //      warp-aggregated 11-bit histogram ----
    float sum = 0.f, mn = INFINITY, mx = -INFINITY;
    #pragma unroll
    for (int k = 0; k < 12; k++) {
        int r = warp + k * 8;            // 0..95
        int c = r >> 5, y = r & 31;
        size_t base = ((((size_t)b * CC + c) * TT + t) * HH + (size_t)(i * GS + y)) * WW
                      + (size_t)(j * GS);
        float val = v[base + lane];
        sum += val;
        mn = fminf(mn, val);
        mx = fmaxf(mx, val);
        uint32_t u = xform(val);
        s[r * 32 + lane] = u;
        int bin = (int)(u >> 21);
        unsigned mk = __match_any_sync(0xffffffffu, bin);
        if (lane == (__ffs(mk) - 1)) atomicAdd(&hist[bin], __popc(mk));
    }
    #pragma unroll
    for (int off = 16; off > 0; off >>= 1) {
        sum += __shfl_down_sync(0xffffffffu, sum, off);
        mn = fminf(mn, __shfl_down_sync(0xffffffffu, mn, off));
        mx = fmaxf(mx, __shfl_down_sync(0xffffffffu, mx, off));
    }
    if (lane == 0) { rf[warp] = sum; rf[8 + warp] = mn; rf[16 + warp] = mx; }
    __syncthreads();
    if (tid == 0) {
        float S = 0.f, MN = INFINITY, MX = -INFINITY;
        #pragma unroll
        for (int w = 0; w < 8; w++) { S += rf[w]; MN = fminf(MN, rf[8+w]); MX = fmaxf(MX, rf[16+w]); }
        bc[0] = S * (1.0f / (float)NPP);
        bc[1] = MN; bc[2] = MX;
    }
    __syncthreads();
    const float mean = bc[0];

    // ---- central moments (two-pass, fp32) ----
    float m2 = 0.f, m3 = 0.f, m4 = 0.f;
    #pragma unroll
    for (int k = 0; k < 12; k++) {
        float x = unxform(s[tid + k * 256]);
        float d = x - mean;
        float d2 = d * d;
        m2 += d2; m3 += d2 * d; m4 += d2 * d2;
    }
    #pragma unroll
    for (int off = 16; off > 0; off >>= 1) {
        m2 += __shfl_down_sync(0xffffffffu, m2, off);
        m3 += __shfl_down_sync(0xffffffffu, m3, off);
        m4 += __shfl_down_sync(0xffffffffu, m4, off);
    }
    if (lane == 0) { rf[warp] = m2; rf[8 + warp] = m3; rf[16 + warp] = m4; }
    __syncthreads();
    if (tid == 0) {
        float M2 = 0.f, M3 = 0.f, M4 = 0.f;
        #pragma unroll
        for (int w = 0; w < 8; w++) { M2 += rf[w]; M3 += rf[8+w]; M4 += rf[16+w]; }
        bc[3] = M2; bc[4] = M3; bc[5] = M4;
    }

    // ---- exclusive prefix scan of hist[2048], in place ----
    {
        int base = tid * 8;
        int vals[8];
        int lsum = 0;
        #pragma unroll
        for (int k = 0; k < 8; k++) {
            vals[k] = hist[base + k];
            int tpv = lsum; lsum += vals[k]; vals[k] = tpv;   // exclusive within thread
        }
        int vinc = lsum;
        #pragma unroll
        for (int off = 1; off < 32; off <<= 1) {
            int n = __shfl_up_sync(0xffffffffu, vinc, off);
            if (lane >= off) vinc += n;
        }
        if (lane == 31) wsum[warp] = vinc;
        __syncthreads();
        if (tid == 0) {
            int acc = 0;
            #pragma unroll
            for (int k = 0; k < 8; k++) { int tv = wsum[k]; wsum[k] = acc; acc += tv; }
        }
        __syncthreads();
        int thr_excl = wsum[warp] + (vinc - lsum);
        #pragma unroll
        for (int k = 0; k < 8; k++) hist[base + k] = thr_excl + vals[k];
    }
    __syncthreads();

    // ---- select bins for the 5 target ranks (thread 0, binary search) ----
    if (tid == 0) {
        const int ranks[5] = {767, 768, 1535, 2303, 2304};
        int nb = 0, off = 0;
        #pragma unroll
        for (int k = 0; k < 5; k++) {
            int r = ranks[k];
            int lo = 0, hi = 2047;
            while (lo < hi) {                      // largest bin with cum <= r
                int mid = (lo + hi + 1) >> 1;
                if (hist[mid] <= r) lo = mid; else hi = mid - 1;
            }
            int cnt = ((lo == 2047) ? NPP : hist[lo + 1]) - hist[lo];
            if (nb == 0 || sel_bin[nb - 1] != lo) {
                sel_bin[nb] = lo; sel_cnt[nb] = cnt; sel_off[nb] = off;
                dcur[nb] = 0; off += cnt; nb++;
            }
            rk_d[k]  = nb - 1;
            rk_in[k] = r - hist[lo];
        }
        sel_nb = nb;
    }
    __syncthreads();
    const int nb = sel_nb;

    // ---- compact candidate-bin elements into buf (warp-aggregated) ----
    #pragma unroll
    for (int k = 0; k < 12; k++) {
        uint32_t u = s[tid + k * 256];
        int bin = (int)(u >> 21);
        int d = -1;
        for (int q = 0; q < nb; q++) if (bin == sel_bin[q]) d = q;
        unsigned mk = __match_any_sync(0xffffffffu, d);
        if (d >= 0) {
            int leader = __ffs(mk) - 1;
            int rpos = __popc(mk & ((1u << lane) - 1u));
            int basepos = 0;
            if (lane == leader) basepos = atomicAdd(&dcur[d], __popc(mk));
            basepos = __shfl_sync(mk, basepos, leader);
            buf[sel_off[d] + basepos + rpos] = u;
        }
    }
    __syncthreads();

    // ---- exact rank within each bucket: all-pairs count (tie-aware) ----
    for (int d = 0; d < nb; d++) {
        const int off = sel_off[d], cnt = sel_cnt[d];
        for (int idx = tid; idx < cnt; idx += 256) {
            uint32_t key = buf[off + idx];
            int less = 0, eq = 0;
            for (int m = 0; m < cnt; m++) {
                uint32_t c = buf[off + m];     // lockstep -> broadcast
                less += (c < key);
                eq   += (c == key);
            }
            #pragma unroll
            for (int k = 0; k < 5; k++) {
                if (rk_d[k] == d) {
                    int r = rk_in[k];
                    if (r >= less && r < less + eq) resv[k] = unxform(key);
                }
            }
        }
    }
    __syncthreads();

    if (tid == 0) {
        const float n = (float)NPP;
        float M2 = bc[3], M3 = bc[4], M4 = bc[5];
        float sd = sqrtf(M2 / (n - 1.0f));
        float sde = sd + 1e-8f;
        float energy = M2 / n + mean * mean;
        float rms = sqrtf(energy + 1e-8f);
        float inv3 = 1.0f / (sde * sde * sde);
        float skew = (M3 / n) * inv3;
        float kurt = (M4 / n) * inv3 / sde - 3.0f;
        float q25 = resv[0] * 0.25f + resv[1] * 0.75f;
        float q75 = resv[3] * 0.75f + resv[4] * 0.25f;

        float* o = out + (size_t)p * 10;
        o[0] = mean; o[1] = sd; o[2] = bc[1]; o[3] = bc[2]; o[4] = energy;
        o[5] = rms;  o[6] = skew; o[7] = kurt; o[8] = resv[2]; o[9] = q75 - q25;
    }
}

__device__ __forceinline__ int tau_t(int t) {
    int c = 0;
    if (t + 1 < TT) c++;
    if (t - 1 >= 0) c++;
    if (t + 2 < TT) c++;
    if (t - 2 >= 0) c++;
    return c;
}

__global__ void edge_kernel(float* __restrict__ out)
{
    int node = blockIdx.x * blockDim.x + threadIdx.x;
    if (node >= NODES) return;
    int t = node / NPF;
    int rem = node % NPF;
    int i = rem / GW;
    int j = rem % GW;

    int mt = t < 30 ? t : 30;
    int cum_tau = (t > 0 ? 2 : 0) + (t > 1 ? 3 : 0)
                + 4 * (mt > 2 ? (mt - 2) : 0) + (t > 30 ? 3 : 0);
    int taut = tau_t(t);
    int rowpref = (i == 0) ? 0 : (31 + 50 * (i - 1));
    int ci = (i == 0 || i == GH - 1) ? 2 : 3;
    int cumcj = (j > 0 ? 2 : 0) + 3 * (j > 1 ? (j - 1) : 0);
    int sp = rowpref + ci * cumcj - j;
    int off = 312 * t + 49 * cum_tau + sp + rem * taut;

    const int di[8] = {-1,-1,-1, 0, 0, 1, 1, 1};
    const int dj[8] = {-1, 0, 1,-1, 1,-1, 0, 1};
    int e = off;
    float fnode = (float)node;
    #pragma unroll
    for (int q = 0; q < 8; q++) {
        int ni = i + di[q], nj = j + dj[q];
        if (ni >= 0 && ni < GH && nj >= 0 && nj < GW) {
            out[e]         = fnode;
            out[NEDGE + e] = (float)(t * NPF + ni * GW + nj);
            e++;
        }
    }
    const int dts[4] = {1, -1, 2, -2};
    #pragma unroll
    for (int q = 0; q < 4; q++) {
        int tt2 = t + dts[q];
        if (tt2 >= 0 && tt2 < TT) {
            out[e]         = fnode;
            out[NEDGE + e] = (float)(tt2 * NPF + i * GW + j);
            e++;
        }
    }
}

extern "C" void kernel_launch(void* const* d_in, const int* in_sizes, int n_in,
                              void* d_out, int out_size)
{
    const float* video = (const float*)d_in[0];
    float* out = (float*)d_out;

    feat_kernel<<<NPATCH, 256>>>(video, out);

    if (out_size >= XFLOATS + 2 * NEDGE) {
        edge_kernel<<<(NODES + 255) / 256, 256>>>(out + XFLOATS);
    }
}